// round 13
// baseline (speedup 1.0000x reference)
#include <cuda_runtime.h>
#include <cuda_bf16.h>

#define N_TOK 512
#define DIMC  1024
#define HEADS 16
#define DH    64
#define PP    32
#define PH    16   // P2

typedef unsigned long long ull;

// ---------------- scratch (device globals; no allocations allowed) -----------
__device__ float g_q[HEADS * N_TOK * DH];    // 2 MB
__device__ float g_k[HEADS * N_TOK * DH];    // 2 MB
__device__ float g_v[HEADS * N_TOK * DH];    // 2 MB
__device__ float g_a[HEADS * N_TOK * PP];    // 1 MB
__device__ float g_c[HEADS * N_TOK * PP];    // 1 MB (b1 folded in)
__device__ float g_ctx[N_TOK * DIMC];        // 2 MB
__device__ float g_part[2 * N_TOK * 3072];   // 12.6 MB split-K partials (max of both GEMMs)

// ---------------- f32x2 packed-FMA helpers (Blackwell) -----------------------
__device__ __forceinline__ ull pack2(float a, float b) {
    ull r; asm("mov.b64 %0, {%1,%2};" : "=l"(r) : "f"(a), "f"(b)); return r;
}
__device__ __forceinline__ ull fma2(ull a, ull b, ull c) {
    ull d; asm("fma.rn.f32x2 %0, %1, %2, %3;" : "=l"(d) : "l"(a), "l"(b), "l"(c)); return d;
}
__device__ __forceinline__ ull mul2(ull a, ull b) {
    ull d; asm("mul.rn.f32x2 %0, %1, %2;" : "=l"(d) : "l"(a), "l"(b)); return d;
}
__device__ __forceinline__ float2 unpack2(ull v) {
    float2 r; asm("mov.b64 {%0,%1}, %2;" : "=f"(r.x), "=f"(r.y) : "l"(v)); return r;
}

// =============================================================================
// GEMM v2: C_part[z] = A[M=512][Kz] * B[N][Kz]^T  (per split-K chunk z)
// 64x64 block tile, 128 threads, 4(M)x8(N) micro-tile, kc=16, double-buffered.
// Always writes fp32 partials to g_part[(z*512+m)*NCOLS + n]; reduce fused later.
// =============================================================================
template <int NCOLS, int SPLITK, bool ACTX>
__global__ __launch_bounds__(128) void gemm2(const float* __restrict__ Ain,
                                             const float* __restrict__ B)
{
    const float* A = ACTX ? g_ctx : Ain;
    __shared__ __align__(16) float As[2][16][64];
    __shared__ __align__(16) float Bs[2][16][64];

    const int t  = threadIdx.x;
    const int m0 = blockIdx.y * 64, n0 = blockIdx.x * 64;
    const int z  = blockIdx.z;
    const int kbase = z * (DIMC / SPLITK);
    const int NT = (DIMC / SPLITK) / 16;

    const int lr  = t & 63;          // load row within tile
    const int lc0 = (t >> 6) * 2;    // first of two f4 k-columns this thread loads

    const int tx = t & 7;            // n-group (8 outputs)
    const int ty = t >> 3;           // m-group (4 outputs)

    ull acc[4][4];
#pragma unroll
    for (int i = 0; i < 4; i++)
#pragma unroll
        for (int j = 0; j < 4; j++) acc[i][j] = 0ULL;

    const float* Ap = A + (size_t)(m0 + lr) * DIMC + kbase + lc0 * 4;
    const float* Bp = B + (size_t)(n0 + lr) * DIMC + kbase + lc0 * 4;

    float4 pa0 = *(const float4*)(Ap);
    float4 pa1 = *(const float4*)(Ap + 4);
    float4 pb0 = *(const float4*)(Bp);
    float4 pb1 = *(const float4*)(Bp + 4);
#pragma unroll
    {
        As[0][lc0 * 4 + 0][lr] = pa0.x; As[0][lc0 * 4 + 1][lr] = pa0.y;
        As[0][lc0 * 4 + 2][lr] = pa0.z; As[0][lc0 * 4 + 3][lr] = pa0.w;
        As[0][lc0 * 4 + 4][lr] = pa1.x; As[0][lc0 * 4 + 5][lr] = pa1.y;
        As[0][lc0 * 4 + 6][lr] = pa1.z; As[0][lc0 * 4 + 7][lr] = pa1.w;
        Bs[0][lc0 * 4 + 0][lr] = pb0.x; Bs[0][lc0 * 4 + 1][lr] = pb0.y;
        Bs[0][lc0 * 4 + 2][lr] = pb0.z; Bs[0][lc0 * 4 + 3][lr] = pb0.w;
        Bs[0][lc0 * 4 + 4][lr] = pb1.x; Bs[0][lc0 * 4 + 5][lr] = pb1.y;
        Bs[0][lc0 * 4 + 6][lr] = pb1.z; Bs[0][lc0 * 4 + 7][lr] = pb1.w;
    }
    __syncthreads();

    for (int tt = 0; tt < NT; tt++) {
        const int cur = tt & 1, nxt = cur ^ 1;
        if (tt + 1 < NT) {
            int off = (tt + 1) * 16;
            pa0 = *(const float4*)(Ap + off);
            pa1 = *(const float4*)(Ap + off + 4);
            pb0 = *(const float4*)(Bp + off);
            pb1 = *(const float4*)(Bp + off + 4);
        }
#pragma unroll
        for (int kk = 0; kk < 16; kk++) {
            float4 a4  = *(const float4*)&As[cur][kk][ty << 2];
            float4 b4a = *(const float4*)&Bs[cur][kk][tx << 3];
            float4 b4b = *(const float4*)&Bs[cur][kk][(tx << 3) + 4];
            ull b0 = pack2(b4a.x, b4a.y), b1 = pack2(b4a.z, b4a.w);
            ull b2 = pack2(b4b.x, b4b.y), b3 = pack2(b4b.z, b4b.w);
            ull a0 = pack2(a4.x, a4.x), a1 = pack2(a4.y, a4.y);
            ull a2 = pack2(a4.z, a4.z), a3 = pack2(a4.w, a4.w);
            acc[0][0] = fma2(a0, b0, acc[0][0]); acc[0][1] = fma2(a0, b1, acc[0][1]);
            acc[0][2] = fma2(a0, b2, acc[0][2]); acc[0][3] = fma2(a0, b3, acc[0][3]);
            acc[1][0] = fma2(a1, b0, acc[1][0]); acc[1][1] = fma2(a1, b1, acc[1][1]);
            acc[1][2] = fma2(a1, b2, acc[1][2]); acc[1][3] = fma2(a1, b3, acc[1][3]);
            acc[2][0] = fma2(a2, b0, acc[2][0]); acc[2][1] = fma2(a2, b1, acc[2][1]);
            acc[2][2] = fma2(a2, b2, acc[2][2]); acc[2][3] = fma2(a2, b3, acc[2][3]);
            acc[3][0] = fma2(a3, b0, acc[3][0]); acc[3][1] = fma2(a3, b1, acc[3][1]);
            acc[3][2] = fma2(a3, b2, acc[3][2]); acc[3][3] = fma2(a3, b3, acc[3][3]);
        }
        if (tt + 1 < NT) {
            As[nxt][lc0 * 4 + 0][lr] = pa0.x; As[nxt][lc0 * 4 + 1][lr] = pa0.y;
            As[nxt][lc0 * 4 + 2][lr] = pa0.z; As[nxt][lc0 * 4 + 3][lr] = pa0.w;
            As[nxt][lc0 * 4 + 4][lr] = pa1.x; As[nxt][lc0 * 4 + 5][lr] = pa1.y;
            As[nxt][lc0 * 4 + 6][lr] = pa1.z; As[nxt][lc0 * 4 + 7][lr] = pa1.w;
            Bs[nxt][lc0 * 4 + 0][lr] = pb0.x; Bs[nxt][lc0 * 4 + 1][lr] = pb0.y;
            Bs[nxt][lc0 * 4 + 2][lr] = pb0.z; Bs[nxt][lc0 * 4 + 3][lr] = pb0.w;
            Bs[nxt][lc0 * 4 + 4][lr] = pb1.x; Bs[nxt][lc0 * 4 + 5][lr] = pb1.y;
            Bs[nxt][lc0 * 4 + 6][lr] = pb1.z; Bs[nxt][lc0 * 4 + 7][lr] = pb1.w;
        }
        __syncthreads();
    }

#pragma unroll
    for (int im = 0; im < 4; im++) {
        float2 c0 = unpack2(acc[im][0]);
        float2 c1 = unpack2(acc[im][1]);
        float2 c2 = unpack2(acc[im][2]);
        float2 c3 = unpack2(acc[im][3]);
        int m = m0 + (ty << 2) + im;
        size_t base = ((size_t)z * N_TOK + m) * NCOLS + n0 + (tx << 3);
        *(float4*)&g_part[base]     = make_float4(c0.x, c0.y, c1.x, c1.y);
        *(float4*)&g_part[base + 4] = make_float4(c2.x, c2.y, c3.x, c3.y);
    }
}

// reduce 2 K1 partials + scatter qkv -> g_q/g_k/g_v.  o = d*48 + s*16 + h
__global__ __launch_bounds__(256) void rs_k()
{
    int i4 = blockIdx.x * 256 + threadIdx.x;      // 393216 threads, 4 floats each
    int m  = i4 / 768;
    int o0 = (i4 - m * 768) * 4;
    float4 p0 = *(const float4*)&g_part[(size_t)m * 3072 + o0];
    float4 p1 = *(const float4*)&g_part[(size_t)(N_TOK + m) * 3072 + o0];
    float v[4] = {p0.x + p1.x, p0.y + p1.y, p0.z + p1.z, p0.w + p1.w};
#pragma unroll
    for (int io = 0; io < 4; io++) {
        int o  = o0 + io;
        int hh = o & 15;
        int s  = (o >> 4) % 3;
        int dd = o / 48;
        float* dst = (s == 0) ? g_q : (s == 1) ? g_k : g_v;
        dst[((hh * N_TOK) + m) * DH + dd] = v[io];
    }
}

// reduce 4 K4 partials -> final out
__global__ __launch_bounds__(256) void ro_k(float* __restrict__ out)
{
    int i4 = blockIdx.x * 256 + threadIdx.x;      // 131072 threads, 4 floats each
    size_t off = (size_t)i4 * 4;
    float4 p0 = *(const float4*)&g_part[off];
    float4 p1 = *(const float4*)&g_part[off + (size_t)N_TOK * DIMC];
    float4 p2 = *(const float4*)&g_part[off + (size_t)2 * N_TOK * DIMC];
    float4 p3 = *(const float4*)&g_part[off + (size_t)3 * N_TOK * DIMC];
    *(float4*)&out[off] = make_float4(p0.x + p1.x + p2.x + p3.x,
                                      p0.y + p1.y + p2.y + p3.y,
                                      p0.z + p1.z + p2.z + p3.z,
                                      p0.w + p1.w + p2.w + p3.w);
}

// =============================================================================
// K2 : per-head projections (unchanged)
// =============================================================================
__global__ __launch_bounds__(256) void proj_k(const float* __restrict__ Wq_,
                                              const float* __restrict__ bq_,
                                              const float* __restrict__ Wk_,
                                              const float* __restrict__ bk_,
                                              const float* __restrict__ W1_,
                                              const float* __restrict__ b1_)
{
    __shared__ float Ws[PP][65];
    __shared__ float W1s[PP][33];
    __shared__ float qs[64][65];
    __shared__ float qps[64][33];
    __shared__ float bs[PP];
    __shared__ float b1s[PP];

    int t  = threadIdx.x;
    int z  = blockIdx.z, h = blockIdx.y, n0 = blockIdx.x * 64;
    const float* W    = z ? Wk_ : Wq_;
    const float* bias = z ? bk_ : bq_;
    const float* src  = z ? g_k : g_q;
    float*       dst  = z ? g_c : g_a;

    for (int idx = t; idx < PP * DH; idx += 256) { int p = idx >> 6, dd = idx & 63; Ws[p][dd] = W[idx]; }
    for (int idx = t; idx < PP * PP; idx += 256) { int q = idx >> 5, p = idx & 31; W1s[q][p] = W1_[q * (2 * PP) + z * PP + p]; }
    if (t < PP) { bs[t] = bias[t]; b1s[t] = b1_[t]; }
    for (int idx = t; idx < 64 * DH; idx += 256) {
        int nl = idx >> 6, dd = idx & 63;
        qs[nl][dd] = src[((h * N_TOK) + n0 + nl) * DH + dd];
    }
    __syncthreads();

    int p = t & 31, g8 = t >> 5;
#pragma unroll
    for (int m = 0; m < 8; m++) {
        int nl = g8 * 8 + m;
        float s = bs[p];
#pragma unroll 8
        for (int dd = 0; dd < DH; dd++) s += qs[nl][dd] * Ws[p][dd];
        qps[nl][p] = s;
    }
    __syncthreads();
#pragma unroll
    for (int m = 0; m < 8; m++) {
        int nl = g8 * 8 + m;
        float s = z ? b1s[p] : 0.f;
#pragma unroll 8
        for (int pp = 0; pp < PP; pp++) s += qps[nl][pp] * W1s[p][pp];
        dst[((h * N_TOK) + n0 + nl) * PP + p] = s;
    }
}

// =============================================================================
// K3 : flash attention with MLP scores (ib reversed so heavy blocks start first)
// =============================================================================
__global__ __launch_bounds__(256) void attn_k(const float* __restrict__ W2_,
                                              const float* __restrict__ b2_,
                                              const float* __restrict__ W3_,
                                              const float* __restrict__ b3_)
{
    __shared__ __align__(16) float as_[PP][33];
    __shared__ __align__(16) float cs_[PP][33];
    __shared__ __align__(16) float Vs[32][65];
    __shared__ __align__(16) float Ss[32][36];
    __shared__ __align__(16) float W2c[PP][PH];
    __shared__ float m_s[32], l_s[32], sc_s[32];

    int t  = threadIdx.x;
    int h  = blockIdx.y;
    int ib = gridDim.x - 1 - blockIdx.x;   // heavy (near-diagonal-full) blocks first
    int i0 = ib * 32;

    for (int idx = t; idx < PH * PP; idx += 256) { int q = idx >> 5, p = idx & 31; W2c[p][q] = W2_[idx]; }
    for (int idx = t; idx < 32 * PP; idx += 256) {
        int ii = idx >> 5, p = idx & 31;
        as_[p][ii] = g_a[((h * N_TOK) + i0 + ii) * PP + p];
    }
    if (t < 32) { m_s[t] = -1e30f; l_s[t] = 0.f; }

    float w3r[PH];
#pragma unroll
    for (int q = 0; q < PH; q++) w3r[q] = W3_[q];
    ull b2p[8];
    {
        const ull* b2u = (const ull*)b2_;
#pragma unroll
        for (int qq = 0; qq < 8; qq++) b2p[qq] = b2u[qq];
    }
    float b3v = b3_[0];

    ull acc[8];
#pragma unroll
    for (int k = 0; k < 8; k++) acc[k] = 0ULL;

    int jc = t & 31, rbase = t >> 5;
    int dd = t & 63, prow = t >> 6;

    for (int jt = 0; jt <= ib; jt++) {
        int j0 = jt * 32;
        __syncthreads();
        for (int idx = t; idx < 32 * PP; idx += 256) {
            int jj = idx >> 5, p = idx & 31;
            cs_[p][jj] = g_c[((h * N_TOK) + j0 + jj) * PP + p];
        }
        for (int idx = t; idx < 32 * DH; idx += 256) {
            int jj = idx >> 6, d2 = idx & 63;
            Vs[jj][d2] = g_v[((h * N_TOK) + j0 + jj) * DH + d2];
        }
        __syncthreads();

        ull h2p[4][8];
#pragma unroll
        for (int r = 0; r < 4; r++)
#pragma unroll
            for (int qq = 0; qq < 8; qq++) h2p[r][qq] = b2p[qq];

#pragma unroll 4
        for (int p = 0; p < PP; p++) {
            float cj = cs_[p][jc];
            ull w2v[8];
            const ull* wrow = (const ull*)&W2c[p][0];
#pragma unroll
            for (int qq = 0; qq < 8; qq++) w2v[qq] = wrow[qq];
#pragma unroll
            for (int r = 0; r < 4; r++) {
                float h1 = fmaxf(as_[p][rbase + 8 * r] + cj, 0.f);
                ull h11 = pack2(h1, h1);
#pragma unroll
                for (int qq = 0; qq < 8; qq++) h2p[r][qq] = fma2(h11, w2v[qq], h2p[r][qq]);
            }
        }
#pragma unroll
        for (int r = 0; r < 4; r++) {
            float s = b3v;
#pragma unroll
            for (int qq = 0; qq < 8; qq++) {
                float2 hq = unpack2(h2p[r][qq]);
                s += w3r[2 * qq]     * fmaxf(hq.x, 0.f);
                s += w3r[2 * qq + 1] * fmaxf(hq.y, 0.f);
            }
            int irow = rbase + 8 * r;
            if (j0 + jc > i0 + irow) s = -1e30f;
            Ss[irow][jc] = s;
        }
        __syncthreads();

        {
            int row = t >> 3, c8 = t & 7;
            float mx = -1e30f;
#pragma unroll
            for (int u = 0; u < 4; u++) mx = fmaxf(mx, Ss[row][c8 * 4 + u]);
            mx = fmaxf(mx, __shfl_xor_sync(0xffffffffu, mx, 1));
            mx = fmaxf(mx, __shfl_xor_sync(0xffffffffu, mx, 2));
            mx = fmaxf(mx, __shfl_xor_sync(0xffffffffu, mx, 4));
            float mnew = fmaxf(m_s[row], mx);
            float sum = 0.f;
#pragma unroll
            for (int u = 0; u < 4; u++) {
                float e = __expf(Ss[row][c8 * 4 + u] - mnew);
                Ss[row][c8 * 4 + u] = e;
                sum += e;
            }
            sum += __shfl_xor_sync(0xffffffffu, sum, 1);
            sum += __shfl_xor_sync(0xffffffffu, sum, 2);
            sum += __shfl_xor_sync(0xffffffffu, sum, 4);
            if (c8 == 0) {
                float scl = __expf(m_s[row] - mnew);
                sc_s[row] = scl;
                l_s[row]  = l_s[row] * scl + sum;
                m_s[row]  = mnew;
            }
        }
        __syncthreads();

#pragma unroll
        for (int k = 0; k < 8; k++) {
            float scl = sc_s[prow + 4 * k];
            acc[k] = mul2(acc[k], pack2(scl, scl));
        }
#pragma unroll 8
        for (int j = 0; j < 32; j += 2) {
            ull v2 = pack2(Vs[j][dd], Vs[j + 1][dd]);
#pragma unroll
            for (int k = 0; k < 8; k++) {
                int ir = prow + 4 * k;
                ull pj = *(const ull*)&Ss[ir][j];
                acc[k] = fma2(pj, v2, acc[k]);
            }
        }
    }

    __syncthreads();
#pragma unroll
    for (int k = 0; k < 8; k++) {
        int ir = prow + 4 * k;
        float2 a2 = unpack2(acc[k]);
        float o = __fdividef(a2.x + a2.y, l_s[ir]);
        g_ctx[(size_t)(i0 + ir) * DIMC + h * DH + dd] = o;
    }
}

// =============================================================================
extern "C" void kernel_launch(void* const* d_in, const int* in_sizes, int n_in,
                              void* d_out, int out_size)
{
    const float* x    = (const float*)d_in[0];
    const float* Wqkv = (const float*)d_in[1];
    const float* Wout = (const float*)d_in[2];
    const float* Wq   = (const float*)d_in[3];
    const float* bq   = (const float*)d_in[4];
    const float* Wk   = (const float*)d_in[5];
    const float* bk   = (const float*)d_in[6];
    const float* W1   = (const float*)d_in[7];
    const float* b1   = (const float*)d_in[8];
    const float* W2   = (const float*)d_in[9];
    const float* b2   = (const float*)d_in[10];
    const float* W3   = (const float*)d_in[11];
    const float* b3   = (const float*)d_in[12];
    float* out = (float*)d_out;

    // K1: qkv partials (split-K=2, 768 blocks) then fused reduce+scatter
    gemm2<3072, 2, false><<<dim3(48, 8, 2), 128>>>(x, Wqkv);
    rs_k<<<1536, 256>>>();
    // K2: a/c projections
    proj_k<<<dim3(8, 16, 2), 256>>>(Wq, bq, Wk, bk, W1, b1);
    // K3: MLP-scored causal flash attention -> g_ctx
    attn_k<<<dim3(16, 16), 256>>>(W2, b2, W3, b3);
    // K4: out partials (split-K=4, 512 blocks) then reduce
    gemm2<1024, 4, true><<<dim3(16, 8, 4), 128>>>(nullptr, Wout);
    ro_k<<<512, 256>>>(out);
}

// round 14
// speedup vs baseline: 1.0007x; 1.0007x over previous
#include <cuda_runtime.h>
#include <cuda_bf16.h>

#define N_TOK 512
#define DIMC  1024
#define HEADS 16
#define DH    64
#define PP    32
#define PH    16   // P2

typedef unsigned long long ull;

// ---------------- scratch (device globals; no allocations allowed) -----------
__device__ float g_q[HEADS * N_TOK * DH];    // 2 MB
__device__ float g_k[HEADS * N_TOK * DH];    // 2 MB
__device__ float g_v[HEADS * N_TOK * DH];    // 2 MB
__device__ float g_a[HEADS * N_TOK * PP];    // 1 MB
__device__ float g_c[HEADS * N_TOK * PP];    // 1 MB (b1 folded in)
__device__ float g_ctx[N_TOK * DIMC];        // 2 MB
__device__ float g_part[2 * N_TOK * 3072];   // 12.6 MB split-K partials (max of both GEMMs)

// ---------------- f32x2 packed-FMA helpers (Blackwell) -----------------------
__device__ __forceinline__ ull pack2(float a, float b) {
    ull r; asm("mov.b64 %0, {%1,%2};" : "=l"(r) : "f"(a), "f"(b)); return r;
}
__device__ __forceinline__ ull fma2(ull a, ull b, ull c) {
    ull d; asm("fma.rn.f32x2 %0, %1, %2, %3;" : "=l"(d) : "l"(a), "l"(b), "l"(c)); return d;
}
__device__ __forceinline__ ull mul2(ull a, ull b) {
    ull d; asm("mul.rn.f32x2 %0, %1, %2;" : "=l"(d) : "l"(a), "l"(b)); return d;
}
__device__ __forceinline__ float2 unpack2(ull v) {
    float2 r; asm("mov.b64 {%0,%1}, %2;" : "=f"(r.x), "=f"(r.y) : "l"(v)); return r;
}

// =============================================================================
// GEMM v2: C_part[z] = A[M=512][Kz] * B[N][Kz]^T  (per split-K chunk z)
// 64x64 block tile, 128 threads, 4(M)x8(N) micro-tile, kc=16, double-buffered.
// Always writes fp32 partials to g_part[(z*512+m)*NCOLS + n]; reduce fused later.
// =============================================================================
template <int NCOLS, int SPLITK, bool ACTX>
__global__ __launch_bounds__(128) void gemm2(const float* __restrict__ Ain,
                                             const float* __restrict__ B)
{
    const float* A = ACTX ? g_ctx : Ain;
    __shared__ __align__(16) float As[2][16][64];
    __shared__ __align__(16) float Bs[2][16][64];

    const int t  = threadIdx.x;
    const int m0 = blockIdx.y * 64, n0 = blockIdx.x * 64;
    const int z  = blockIdx.z;
    const int kbase = z * (DIMC / SPLITK);
    const int NT = (DIMC / SPLITK) / 16;

    const int lr  = t & 63;          // load row within tile
    const int lc0 = (t >> 6) * 2;    // first of two f4 k-columns this thread loads

    const int tx = t & 7;            // n-group (8 outputs)
    const int ty = t >> 3;           // m-group (4 outputs)

    ull acc[4][4];
#pragma unroll
    for (int i = 0; i < 4; i++)
#pragma unroll
        for (int j = 0; j < 4; j++) acc[i][j] = 0ULL;

    const float* Ap = A + (size_t)(m0 + lr) * DIMC + kbase + lc0 * 4;
    const float* Bp = B + (size_t)(n0 + lr) * DIMC + kbase + lc0 * 4;

    float4 pa0 = *(const float4*)(Ap);
    float4 pa1 = *(const float4*)(Ap + 4);
    float4 pb0 = *(const float4*)(Bp);
    float4 pb1 = *(const float4*)(Bp + 4);
#pragma unroll
    {
        As[0][lc0 * 4 + 0][lr] = pa0.x; As[0][lc0 * 4 + 1][lr] = pa0.y;
        As[0][lc0 * 4 + 2][lr] = pa0.z; As[0][lc0 * 4 + 3][lr] = pa0.w;
        As[0][lc0 * 4 + 4][lr] = pa1.x; As[0][lc0 * 4 + 5][lr] = pa1.y;
        As[0][lc0 * 4 + 6][lr] = pa1.z; As[0][lc0 * 4 + 7][lr] = pa1.w;
        Bs[0][lc0 * 4 + 0][lr] = pb0.x; Bs[0][lc0 * 4 + 1][lr] = pb0.y;
        Bs[0][lc0 * 4 + 2][lr] = pb0.z; Bs[0][lc0 * 4 + 3][lr] = pb0.w;
        Bs[0][lc0 * 4 + 4][lr] = pb1.x; Bs[0][lc0 * 4 + 5][lr] = pb1.y;
        Bs[0][lc0 * 4 + 6][lr] = pb1.z; Bs[0][lc0 * 4 + 7][lr] = pb1.w;
    }
    __syncthreads();

    for (int tt = 0; tt < NT; tt++) {
        const int cur = tt & 1, nxt = cur ^ 1;
        if (tt + 1 < NT) {
            int off = (tt + 1) * 16;
            pa0 = *(const float4*)(Ap + off);
            pa1 = *(const float4*)(Ap + off + 4);
            pb0 = *(const float4*)(Bp + off);
            pb1 = *(const float4*)(Bp + off + 4);
        }
#pragma unroll
        for (int kk = 0; kk < 16; kk++) {
            float4 a4  = *(const float4*)&As[cur][kk][ty << 2];
            float4 b4a = *(const float4*)&Bs[cur][kk][tx << 3];
            float4 b4b = *(const float4*)&Bs[cur][kk][(tx << 3) + 4];
            ull b0 = pack2(b4a.x, b4a.y), b1 = pack2(b4a.z, b4a.w);
            ull b2 = pack2(b4b.x, b4b.y), b3 = pack2(b4b.z, b4b.w);
            ull a0 = pack2(a4.x, a4.x), a1 = pack2(a4.y, a4.y);
            ull a2 = pack2(a4.z, a4.z), a3 = pack2(a4.w, a4.w);
            acc[0][0] = fma2(a0, b0, acc[0][0]); acc[0][1] = fma2(a0, b1, acc[0][1]);
            acc[0][2] = fma2(a0, b2, acc[0][2]); acc[0][3] = fma2(a0, b3, acc[0][3]);
            acc[1][0] = fma2(a1, b0, acc[1][0]); acc[1][1] = fma2(a1, b1, acc[1][1]);
            acc[1][2] = fma2(a1, b2, acc[1][2]); acc[1][3] = fma2(a1, b3, acc[1][3]);
            acc[2][0] = fma2(a2, b0, acc[2][0]); acc[2][1] = fma2(a2, b1, acc[2][1]);
            acc[2][2] = fma2(a2, b2, acc[2][2]); acc[2][3] = fma2(a2, b3, acc[2][3]);
            acc[3][0] = fma2(a3, b0, acc[3][0]); acc[3][1] = fma2(a3, b1, acc[3][1]);
            acc[3][2] = fma2(a3, b2, acc[3][2]); acc[3][3] = fma2(a3, b3, acc[3][3]);
        }
        if (tt + 1 < NT) {
            As[nxt][lc0 * 4 + 0][lr] = pa0.x; As[nxt][lc0 * 4 + 1][lr] = pa0.y;
            As[nxt][lc0 * 4 + 2][lr] = pa0.z; As[nxt][lc0 * 4 + 3][lr] = pa0.w;
            As[nxt][lc0 * 4 + 4][lr] = pa1.x; As[nxt][lc0 * 4 + 5][lr] = pa1.y;
            As[nxt][lc0 * 4 + 6][lr] = pa1.z; As[nxt][lc0 * 4 + 7][lr] = pa1.w;
            Bs[nxt][lc0 * 4 + 0][lr] = pb0.x; Bs[nxt][lc0 * 4 + 1][lr] = pb0.y;
            Bs[nxt][lc0 * 4 + 2][lr] = pb0.z; Bs[nxt][lc0 * 4 + 3][lr] = pb0.w;
            Bs[nxt][lc0 * 4 + 4][lr] = pb1.x; Bs[nxt][lc0 * 4 + 5][lr] = pb1.y;
            Bs[nxt][lc0 * 4 + 6][lr] = pb1.z; Bs[nxt][lc0 * 4 + 7][lr] = pb1.w;
        }
        __syncthreads();
    }

#pragma unroll
    for (int im = 0; im < 4; im++) {
        float2 c0 = unpack2(acc[im][0]);
        float2 c1 = unpack2(acc[im][1]);
        float2 c2 = unpack2(acc[im][2]);
        float2 c3 = unpack2(acc[im][3]);
        int m = m0 + (ty << 2) + im;
        size_t base = ((size_t)z * N_TOK + m) * NCOLS + n0 + (tx << 3);
        *(float4*)&g_part[base]     = make_float4(c0.x, c0.y, c1.x, c1.y);
        *(float4*)&g_part[base + 4] = make_float4(c2.x, c2.y, c3.x, c3.y);
    }
}

// reduce 2 K1 partials + scatter qkv -> g_q/g_k/g_v.  o = d*48 + s*16 + h
__global__ __launch_bounds__(256) void rs_k()
{
    int i4 = blockIdx.x * 256 + threadIdx.x;      // 393216 threads, 4 floats each
    int m  = i4 / 768;
    int o0 = (i4 - m * 768) * 4;
    float4 p0 = *(const float4*)&g_part[(size_t)m * 3072 + o0];
    float4 p1 = *(const float4*)&g_part[(size_t)(N_TOK + m) * 3072 + o0];
    float v[4] = {p0.x + p1.x, p0.y + p1.y, p0.z + p1.z, p0.w + p1.w};
#pragma unroll
    for (int io = 0; io < 4; io++) {
        int o  = o0 + io;
        int hh = o & 15;
        int s  = (o >> 4) % 3;
        int dd = o / 48;
        float* dst = (s == 0) ? g_q : (s == 1) ? g_k : g_v;
        dst[((hh * N_TOK) + m) * DH + dd] = v[io];
    }
}

// reduce 4 K4 partials -> final out
__global__ __launch_bounds__(256) void ro_k(float* __restrict__ out)
{
    int i4 = blockIdx.x * 256 + threadIdx.x;      // 131072 threads, 4 floats each
    size_t off = (size_t)i4 * 4;
    float4 p0 = *(const float4*)&g_part[off];
    float4 p1 = *(const float4*)&g_part[off + (size_t)N_TOK * DIMC];
    float4 p2 = *(const float4*)&g_part[off + (size_t)2 * N_TOK * DIMC];
    float4 p3 = *(const float4*)&g_part[off + (size_t)3 * N_TOK * DIMC];
    *(float4*)&out[off] = make_float4(p0.x + p1.x + p2.x + p3.x,
                                      p0.y + p1.y + p2.y + p3.y,
                                      p0.z + p1.z + p2.z + p3.z,
                                      p0.w + p1.w + p2.w + p3.w);
}

// =============================================================================
// K2 : per-head projections (unchanged)
// =============================================================================
__global__ __launch_bounds__(256) void proj_k(const float* __restrict__ Wq_,
                                              const float* __restrict__ bq_,
                                              const float* __restrict__ Wk_,
                                              const float* __restrict__ bk_,
                                              const float* __restrict__ W1_,
                                              const float* __restrict__ b1_)
{
    __shared__ float Ws[PP][65];
    __shared__ float W1s[PP][33];
    __shared__ float qs[64][65];
    __shared__ float qps[64][33];
    __shared__ float bs[PP];
    __shared__ float b1s[PP];

    int t  = threadIdx.x;
    int z  = blockIdx.z, h = blockIdx.y, n0 = blockIdx.x * 64;
    const float* W    = z ? Wk_ : Wq_;
    const float* bias = z ? bk_ : bq_;
    const float* src  = z ? g_k : g_q;
    float*       dst  = z ? g_c : g_a;

    for (int idx = t; idx < PP * DH; idx += 256) { int p = idx >> 6, dd = idx & 63; Ws[p][dd] = W[idx]; }
    for (int idx = t; idx < PP * PP; idx += 256) { int q = idx >> 5, p = idx & 31; W1s[q][p] = W1_[q * (2 * PP) + z * PP + p]; }
    if (t < PP) { bs[t] = bias[t]; b1s[t] = b1_[t]; }
    for (int idx = t; idx < 64 * DH; idx += 256) {
        int nl = idx >> 6, dd = idx & 63;
        qs[nl][dd] = src[((h * N_TOK) + n0 + nl) * DH + dd];
    }
    __syncthreads();

    int p = t & 31, g8 = t >> 5;
#pragma unroll
    for (int m = 0; m < 8; m++) {
        int nl = g8 * 8 + m;
        float s = bs[p];
#pragma unroll 8
        for (int dd = 0; dd < DH; dd++) s += qs[nl][dd] * Ws[p][dd];
        qps[nl][p] = s;
    }
    __syncthreads();
#pragma unroll
    for (int m = 0; m < 8; m++) {
        int nl = g8 * 8 + m;
        float s = z ? b1s[p] : 0.f;
#pragma unroll 8
        for (int pp = 0; pp < PP; pp++) s += qps[nl][pp] * W1s[p][pp];
        dst[((h * N_TOK) + n0 + nl) * PP + p] = s;
    }
}

// =============================================================================
// K3 : flash attention with MLP scores (ib reversed so heavy blocks start first)
// =============================================================================
__global__ __launch_bounds__(256) void attn_k(const float* __restrict__ W2_,
                                              const float* __restrict__ b2_,
                                              const float* __restrict__ W3_,
                                              const float* __restrict__ b3_)
{
    __shared__ __align__(16) float as_[PP][33];
    __shared__ __align__(16) float cs_[PP][33];
    __shared__ __align__(16) float Vs[32][65];
    __shared__ __align__(16) float Ss[32][36];
    __shared__ __align__(16) float W2c[PP][PH];
    __shared__ float m_s[32], l_s[32], sc_s[32];

    int t  = threadIdx.x;
    int h  = blockIdx.y;
    int ib = gridDim.x - 1 - blockIdx.x;   // heavy (near-diagonal-full) blocks first
    int i0 = ib * 32;

    for (int idx = t; idx < PH * PP; idx += 256) { int q = idx >> 5, p = idx & 31; W2c[p][q] = W2_[idx]; }
    for (int idx = t; idx < 32 * PP; idx += 256) {
        int ii = idx >> 5, p = idx & 31;
        as_[p][ii] = g_a[((h * N_TOK) + i0 + ii) * PP + p];
    }
    if (t < 32) { m_s[t] = -1e30f; l_s[t] = 0.f; }

    float w3r[PH];
#pragma unroll
    for (int q = 0; q < PH; q++) w3r[q] = W3_[q];
    ull b2p[8];
    {
        const ull* b2u = (const ull*)b2_;
#pragma unroll
        for (int qq = 0; qq < 8; qq++) b2p[qq] = b2u[qq];
    }
    float b3v = b3_[0];

    ull acc[8];
#pragma unroll
    for (int k = 0; k < 8; k++) acc[k] = 0ULL;

    int jc = t & 31, rbase = t >> 5;
    int dd = t & 63, prow = t >> 6;

    for (int jt = 0; jt <= ib; jt++) {
        int j0 = jt * 32;
        __syncthreads();
        for (int idx = t; idx < 32 * PP; idx += 256) {
            int jj = idx >> 5, p = idx & 31;
            cs_[p][jj] = g_c[((h * N_TOK) + j0 + jj) * PP + p];
        }
        for (int idx = t; idx < 32 * DH; idx += 256) {
            int jj = idx >> 6, d2 = idx & 63;
            Vs[jj][d2] = g_v[((h * N_TOK) + j0 + jj) * DH + d2];
        }
        __syncthreads();

        ull h2p[4][8];
#pragma unroll
        for (int r = 0; r < 4; r++)
#pragma unroll
            for (int qq = 0; qq < 8; qq++) h2p[r][qq] = b2p[qq];

#pragma unroll 4
        for (int p = 0; p < PP; p++) {
            float cj = cs_[p][jc];
            ull w2v[8];
            const ull* wrow = (const ull*)&W2c[p][0];
#pragma unroll
            for (int qq = 0; qq < 8; qq++) w2v[qq] = wrow[qq];
#pragma unroll
            for (int r = 0; r < 4; r++) {
                float h1 = fmaxf(as_[p][rbase + 8 * r] + cj, 0.f);
                ull h11 = pack2(h1, h1);
#pragma unroll
                for (int qq = 0; qq < 8; qq++) h2p[r][qq] = fma2(h11, w2v[qq], h2p[r][qq]);
            }
        }
#pragma unroll
        for (int r = 0; r < 4; r++) {
            float s = b3v;
#pragma unroll
            for (int qq = 0; qq < 8; qq++) {
                float2 hq = unpack2(h2p[r][qq]);
                s += w3r[2 * qq]     * fmaxf(hq.x, 0.f);
                s += w3r[2 * qq + 1] * fmaxf(hq.y, 0.f);
            }
            int irow = rbase + 8 * r;
            if (j0 + jc > i0 + irow) s = -1e30f;
            Ss[irow][jc] = s;
        }
        __syncthreads();

        {
            int row = t >> 3, c8 = t & 7;
            float mx = -1e30f;
#pragma unroll
            for (int u = 0; u < 4; u++) mx = fmaxf(mx, Ss[row][c8 * 4 + u]);
            mx = fmaxf(mx, __shfl_xor_sync(0xffffffffu, mx, 1));
            mx = fmaxf(mx, __shfl_xor_sync(0xffffffffu, mx, 2));
            mx = fmaxf(mx, __shfl_xor_sync(0xffffffffu, mx, 4));
            float mnew = fmaxf(m_s[row], mx);
            float sum = 0.f;
#pragma unroll
            for (int u = 0; u < 4; u++) {
                float e = __expf(Ss[row][c8 * 4 + u] - mnew);
                Ss[row][c8 * 4 + u] = e;
                sum += e;
            }
            sum += __shfl_xor_sync(0xffffffffu, sum, 1);
            sum += __shfl_xor_sync(0xffffffffu, sum, 2);
            sum += __shfl_xor_sync(0xffffffffu, sum, 4);
            if (c8 == 0) {
                float scl = __expf(m_s[row] - mnew);
                sc_s[row] = scl;
                l_s[row]  = l_s[row] * scl + sum;
                m_s[row]  = mnew;
            }
        }
        __syncthreads();

#pragma unroll
        for (int k = 0; k < 8; k++) {
            float scl = sc_s[prow + 4 * k];
            acc[k] = mul2(acc[k], pack2(scl, scl));
        }
#pragma unroll 8
        for (int j = 0; j < 32; j += 2) {
            ull v2 = pack2(Vs[j][dd], Vs[j + 1][dd]);
#pragma unroll
            for (int k = 0; k < 8; k++) {
                int ir = prow + 4 * k;
                ull pj = *(const ull*)&Ss[ir][j];
                acc[k] = fma2(pj, v2, acc[k]);
            }
        }
    }

    __syncthreads();
#pragma unroll
    for (int k = 0; k < 8; k++) {
        int ir = prow + 4 * k;
        float2 a2 = unpack2(acc[k]);
        float o = __fdividef(a2.x + a2.y, l_s[ir]);
        g_ctx[(size_t)(i0 + ir) * DIMC + h * DH + dd] = o;
    }
}

// =============================================================================
extern "C" void kernel_launch(void* const* d_in, const int* in_sizes, int n_in,
                              void* d_out, int out_size)
{
    const float* x    = (const float*)d_in[0];
    const float* Wqkv = (const float*)d_in[1];
    const float* Wout = (const float*)d_in[2];
    const float* Wq   = (const float*)d_in[3];
    const float* bq   = (const float*)d_in[4];
    const float* Wk   = (const float*)d_in[5];
    const float* bk   = (const float*)d_in[6];
    const float* W1   = (const float*)d_in[7];
    const float* b1   = (const float*)d_in[8];
    const float* W2   = (const float*)d_in[9];
    const float* b2   = (const float*)d_in[10];
    const float* W3   = (const float*)d_in[11];
    const float* b3   = (const float*)d_in[12];
    float* out = (float*)d_out;

    // K1: qkv partials (split-K=2, 768 blocks) then fused reduce+scatter
    gemm2<3072, 2, false><<<dim3(48, 8, 2), 128>>>(x, Wqkv);
    rs_k<<<1536, 256>>>();
    // K2: a/c projections
    proj_k<<<dim3(8, 16, 2), 256>>>(Wq, bq, Wk, bk, W1, b1);
    // K3: MLP-scored causal flash attention -> g_ctx
    attn_k<<<dim3(16, 16), 256>>>(W2, b2, W3, b3);
    // K4: out partials (split-K=4, 512 blocks) then reduce
    gemm2<1024, 4, true><<<dim3(16, 8, 4), 128>>>(nullptr, Wout);
    ro_k<<<512, 256>>>(out);
}

// round 15
// speedup vs baseline: 1.1878x; 1.1869x over previous
#include <cuda_runtime.h>
#include <cuda_bf16.h>

#define N_TOK 512
#define DIMC  1024
#define HEADS 16
#define DH    64
#define PP    32
#define PH    16   // P2

typedef unsigned long long ull;

// ---------------- scratch (device globals; no allocations allowed) -----------
__device__ float g_q[HEADS * N_TOK * DH];
__device__ float g_k[HEADS * N_TOK * DH];
__device__ float g_v[HEADS * N_TOK * DH];
__device__ float g_a[HEADS * N_TOK * PP];
__device__ float g_c[HEADS * N_TOK * PP];    // b1 folded in
__device__ float g_ctx[N_TOK * DIMC];
__device__ float g_part[2 * N_TOK * 3072];   // split-K partials (12.6 MB max)

// ---------------- f32x2 packed-FMA helpers (Blackwell) -----------------------
__device__ __forceinline__ ull pack2(float a, float b) {
    ull r; asm("mov.b64 %0, {%1,%2};" : "=l"(r) : "f"(a), "f"(b)); return r;
}
__device__ __forceinline__ ull fma2(ull a, ull b, ull c) {
    ull d; asm("fma.rn.f32x2 %0, %1, %2, %3;" : "=l"(d) : "l"(a), "l"(b), "l"(c)); return d;
}
__device__ __forceinline__ ull mul2(ull a, ull b) {
    ull d; asm("mul.rn.f32x2 %0, %1, %2;" : "=l"(d) : "l"(a), "l"(b)); return d;
}
__device__ __forceinline__ float2 unpack2(ull v) {
    float2 r; asm("mov.b64 {%0,%1}, %2;" : "=f"(r.x), "=f"(r.y) : "l"(v)); return r;
}

// =============================================================================
// GEMM (R12-proven inner structure): 64x64 tile, 256 threads, 4x4 micro-tile.
// Split-K over blockIdx.z; partials -> g_part[(z*512+m)*NCOLS + n].
// =============================================================================
template <int NCOLS, int SPLITK, bool ACTX>
__global__ __launch_bounds__(256) void gemm_k(const float* __restrict__ Ain,
                                              const float* __restrict__ B)
{
    const float* A = ACTX ? g_ctx : Ain;
    __shared__ __align__(16) float As[16][64];
    __shared__ __align__(16) float Bs[16][64];

    const int KPER = DIMC / SPLITK;
    int t  = threadIdx.x;
    int tx = t & 15, ty = t >> 4;
    int m0 = blockIdx.y * 64, n0 = blockIdx.x * 64;
    int z  = blockIdx.z;
    int lr = t >> 2, lc = (t & 3) << 2;

    ull acc[4][2];
#pragma unroll
    for (int i = 0; i < 4; i++) { acc[i][0] = 0ULL; acc[i][1] = 0ULL; }

    const float* Aptr = A + (size_t)(m0 + lr) * DIMC + z * KPER + lc;
    const float* Bptr = B + (size_t)(n0 + lr) * DIMC + z * KPER + lc;

    for (int k0 = 0; k0 < KPER; k0 += 16) {
        float4 av = *(const float4*)(Aptr + k0);
        float4 bv = *(const float4*)(Bptr + k0);
        As[lc + 0][lr] = av.x; As[lc + 1][lr] = av.y;
        As[lc + 2][lr] = av.z; As[lc + 3][lr] = av.w;
        Bs[lc + 0][lr] = bv.x; Bs[lc + 1][lr] = bv.y;
        Bs[lc + 2][lr] = bv.z; Bs[lc + 3][lr] = bv.w;
        __syncthreads();
#pragma unroll
        for (int kk = 0; kk < 16; kk++) {
            float4 a4 = *(const float4*)&As[kk][ty << 2];
            float4 b4 = *(const float4*)&Bs[kk][tx << 2];
            ull b01 = pack2(b4.x, b4.y), b23 = pack2(b4.z, b4.w);
            ull a0 = pack2(a4.x, a4.x), a1 = pack2(a4.y, a4.y);
            ull a2 = pack2(a4.z, a4.z), a3 = pack2(a4.w, a4.w);
            acc[0][0] = fma2(a0, b01, acc[0][0]); acc[0][1] = fma2(a0, b23, acc[0][1]);
            acc[1][0] = fma2(a1, b01, acc[1][0]); acc[1][1] = fma2(a1, b23, acc[1][1]);
            acc[2][0] = fma2(a2, b01, acc[2][0]); acc[2][1] = fma2(a2, b23, acc[2][1]);
            acc[3][0] = fma2(a3, b01, acc[3][0]); acc[3][1] = fma2(a3, b23, acc[3][1]);
        }
        __syncthreads();
    }

#pragma unroll
    for (int im = 0; im < 4; im++) {
        float2 c01 = unpack2(acc[im][0]);
        float2 c23 = unpack2(acc[im][1]);
        int m = m0 + (ty << 2) + im;
        size_t base = ((size_t)z * N_TOK + m) * NCOLS + n0 + (tx << 2);
        *(float4*)&g_part[base] = make_float4(c01.x, c01.y, c23.x, c23.y);
    }
}

// reduce 2 K1 partials + scatter qkv -> g_q/g_k/g_v.  o = d*48 + s*16 + h
__global__ __launch_bounds__(256) void rs_k()
{
    int i4 = blockIdx.x * 256 + threadIdx.x;      // 393216 threads, 4 floats each
    int m  = i4 / 768;
    int o0 = (i4 - m * 768) * 4;
    float4 p0 = *(const float4*)&g_part[(size_t)m * 3072 + o0];
    float4 p1 = *(const float4*)&g_part[(size_t)(N_TOK + m) * 3072 + o0];
    float v[4] = {p0.x + p1.x, p0.y + p1.y, p0.z + p1.z, p0.w + p1.w};
#pragma unroll
    for (int io = 0; io < 4; io++) {
        int o  = o0 + io;
        int hh = o & 15;
        int s  = (o >> 4) % 3;
        int dd = o / 48;
        float* dst = (s == 0) ? g_q : (s == 1) ? g_k : g_v;
        dst[((hh * N_TOK) + m) * DH + dd] = v[io];
    }
}

// reduce 4 K4 partials -> final out
__global__ __launch_bounds__(256) void ro_k(float* __restrict__ out)
{
    int i4 = blockIdx.x * 256 + threadIdx.x;      // 131072 threads, 4 floats each
    size_t off = (size_t)i4 * 4;
    float4 p0 = *(const float4*)&g_part[off];
    float4 p1 = *(const float4*)&g_part[off + (size_t)N_TOK * DIMC];
    float4 p2 = *(const float4*)&g_part[off + (size_t)2 * N_TOK * DIMC];
    float4 p3 = *(const float4*)&g_part[off + (size_t)3 * N_TOK * DIMC];
    *(float4*)&out[off] = make_float4(p0.x + p1.x + p2.x + p3.x,
                                      p0.y + p1.y + p2.y + p3.y,
                                      p0.z + p1.z + p2.z + p3.z,
                                      p0.w + p1.w + p2.w + p3.w);
}

// =============================================================================
// K2 : per-head projections (unchanged)
// =============================================================================
__global__ __launch_bounds__(256) void proj_k(const float* __restrict__ Wq_,
                                              const float* __restrict__ bq_,
                                              const float* __restrict__ Wk_,
                                              const float* __restrict__ bk_,
                                              const float* __restrict__ W1_,
                                              const float* __restrict__ b1_)
{
    __shared__ float Ws[PP][65];
    __shared__ float W1s[PP][33];
    __shared__ float qs[64][65];
    __shared__ float qps[64][33];
    __shared__ float bs[PP];
    __shared__ float b1s[PP];

    int t  = threadIdx.x;
    int z  = blockIdx.z, h = blockIdx.y, n0 = blockIdx.x * 64;
    const float* W    = z ? Wk_ : Wq_;
    const float* bias = z ? bk_ : bq_;
    const float* src  = z ? g_k : g_q;
    float*       dst  = z ? g_c : g_a;

    for (int idx = t; idx < PP * DH; idx += 256) { int p = idx >> 6, dd = idx & 63; Ws[p][dd] = W[idx]; }
    for (int idx = t; idx < PP * PP; idx += 256) { int q = idx >> 5, p = idx & 31; W1s[q][p] = W1_[q * (2 * PP) + z * PP + p]; }
    if (t < PP) { bs[t] = bias[t]; b1s[t] = b1_[t]; }
    for (int idx = t; idx < 64 * DH; idx += 256) {
        int nl = idx >> 6, dd = idx & 63;
        qs[nl][dd] = src[((h * N_TOK) + n0 + nl) * DH + dd];
    }
    __syncthreads();

    int p = t & 31, g8 = t >> 5;
#pragma unroll
    for (int m = 0; m < 8; m++) {
        int nl = g8 * 8 + m;
        float s = bs[p];
#pragma unroll 8
        for (int dd = 0; dd < DH; dd++) s += qs[nl][dd] * Ws[p][dd];
        qps[nl][p] = s;
    }
    __syncthreads();
#pragma unroll
    for (int m = 0; m < 8; m++) {
        int nl = g8 * 8 + m;
        float s = z ? b1s[p] : 0.f;
#pragma unroll 8
        for (int pp = 0; pp < PP; pp++) s += qps[nl][pp] * W1s[p][pp];
        dst[((h * N_TOK) + n0 + nl) * PP + p] = s;
    }
}

// =============================================================================
// K3 : flash attention with MLP scores.
// Occupancy 2 blocks/SM: launch_bounds(256,2); w3/b2/b3 in shared;
// inner loop: h11[4] per p, then qq-outer with one w2 pair live at a time.
// =============================================================================
__global__ __launch_bounds__(256, 2) void attn_k(const float* __restrict__ W2_,
                                                 const float* __restrict__ b2_,
                                                 const float* __restrict__ W3_,
                                                 const float* __restrict__ b3_)
{
    __shared__ __align__(16) float as_[PP][33];
    __shared__ __align__(16) float cs_[PP][33];
    __shared__ __align__(16) float Vs[32][65];
    __shared__ __align__(16) float Ss[32][36];
    __shared__ __align__(16) float W2c[PP][PH];   // W2c[p][q]
    __shared__ __align__(16) float w3s[PH];
    __shared__ __align__(16) float b2s[PH];
    __shared__ float m_s[32], l_s[32], sc_s[32], b3s;

    int t  = threadIdx.x;
    int h  = blockIdx.y;
    int ib = gridDim.x - 1 - blockIdx.x;   // heavy blocks first
    int i0 = ib * 32;

    for (int idx = t; idx < PH * PP; idx += 256) { int q = idx >> 5, p = idx & 31; W2c[p][q] = W2_[idx]; }
    for (int idx = t; idx < 32 * PP; idx += 256) {
        int ii = idx >> 5, p = idx & 31;
        as_[p][ii] = g_a[((h * N_TOK) + i0 + ii) * PP + p];
    }
    if (t < 32) { m_s[t] = -1e30f; l_s[t] = 0.f; }
    if (t < PH) { w3s[t] = W3_[t]; b2s[t] = b2_[t]; }
    if (t == 0) { b3s = b3_[0]; }

    ull acc[8];
#pragma unroll
    for (int k = 0; k < 8; k++) acc[k] = 0ULL;

    int jc = t & 31, rbase = t >> 5;     // scoring: col jc, rows rbase+8r
    int dd = t & 63, prow = t >> 6;      // PV: col dd, rows prow+4k

    for (int jt = 0; jt <= ib; jt++) {
        int j0 = jt * 32;
        __syncthreads();   // also covers initial smem loads on first iteration
        for (int idx = t; idx < 32 * PP; idx += 256) {
            int jj = idx >> 5, p = idx & 31;
            cs_[p][jj] = g_c[((h * N_TOK) + j0 + jj) * PP + p];
        }
        for (int idx = t; idx < 32 * DH; idx += 256) {
            int jj = idx >> 6, d2 = idx & 63;
            Vs[jj][d2] = g_v[((h * N_TOK) + j0 + jj) * DH + d2];
        }
        __syncthreads();

        // ---- scoring: 4 (i) x 1 (j) pairs/thread, f32x2 over the 16 q's
        ull h2p[4][8];
#pragma unroll
        for (int r = 0; r < 4; r++)
#pragma unroll
            for (int qq = 0; qq < 8; qq++) h2p[r][qq] = *(const ull*)&b2s[2 * qq];

#pragma unroll 4
        for (int p = 0; p < PP; p++) {
            float cj = cs_[p][jc];
            ull h11[4];
#pragma unroll
            for (int r = 0; r < 4; r++) {
                float h1 = fmaxf(as_[p][rbase + 8 * r] + cj, 0.f);
                h11[r] = pack2(h1, h1);
            }
            const ull* wrow = (const ull*)&W2c[p][0];
#pragma unroll
            for (int qq = 0; qq < 8; qq++) {
                ull w2 = wrow[qq];
                h2p[0][qq] = fma2(h11[0], w2, h2p[0][qq]);
                h2p[1][qq] = fma2(h11[1], w2, h2p[1][qq]);
                h2p[2][qq] = fma2(h11[2], w2, h2p[2][qq]);
                h2p[3][qq] = fma2(h11[3], w2, h2p[3][qq]);
            }
        }
#pragma unroll
        for (int r = 0; r < 4; r++) {
            float s = b3s;
#pragma unroll
            for (int qq = 0; qq < 8; qq++) {
                float2 hq = unpack2(h2p[r][qq]);
                s += w3s[2 * qq]     * fmaxf(hq.x, 0.f);
                s += w3s[2 * qq + 1] * fmaxf(hq.y, 0.f);
            }
            int irow = rbase + 8 * r;
            if (j0 + jc > i0 + irow) s = -1e30f;
            Ss[irow][jc] = s;
        }
        __syncthreads();

        // ---- online softmax: 8 threads per row
        {
            int row = t >> 3, c8 = t & 7;
            float mx = -1e30f;
#pragma unroll
            for (int u = 0; u < 4; u++) mx = fmaxf(mx, Ss[row][c8 * 4 + u]);
            mx = fmaxf(mx, __shfl_xor_sync(0xffffffffu, mx, 1));
            mx = fmaxf(mx, __shfl_xor_sync(0xffffffffu, mx, 2));
            mx = fmaxf(mx, __shfl_xor_sync(0xffffffffu, mx, 4));
            float mnew = fmaxf(m_s[row], mx);
            float sum = 0.f;
#pragma unroll
            for (int u = 0; u < 4; u++) {
                float e = __expf(Ss[row][c8 * 4 + u] - mnew);
                Ss[row][c8 * 4 + u] = e;
                sum += e;
            }
            sum += __shfl_xor_sync(0xffffffffu, sum, 1);
            sum += __shfl_xor_sync(0xffffffffu, sum, 2);
            sum += __shfl_xor_sync(0xffffffffu, sum, 4);
            if (c8 == 0) {
                float scl = __expf(m_s[row] - mnew);
                sc_s[row] = scl;
                l_s[row]  = l_s[row] * scl + sum;
                m_s[row]  = mnew;
            }
        }
        __syncthreads();

        // ---- rescale + P@V (f32x2 pairs over j)
#pragma unroll
        for (int k = 0; k < 8; k++) {
            float scl = sc_s[prow + 4 * k];
            acc[k] = mul2(acc[k], pack2(scl, scl));
        }
#pragma unroll 8
        for (int j = 0; j < 32; j += 2) {
            ull v2 = pack2(Vs[j][dd], Vs[j + 1][dd]);
#pragma unroll
            for (int k = 0; k < 8; k++) {
                int ir = prow + 4 * k;
                ull pj = *(const ull*)&Ss[ir][j];
                acc[k] = fma2(pj, v2, acc[k]);
            }
        }
    }

    __syncthreads();
#pragma unroll
    for (int k = 0; k < 8; k++) {
        int ir = prow + 4 * k;
        float2 a2 = unpack2(acc[k]);
        float o = __fdividef(a2.x + a2.y, l_s[ir]);
        g_ctx[(size_t)(i0 + ir) * DIMC + h * DH + dd] = o;
    }
}

// =============================================================================
extern "C" void kernel_launch(void* const* d_in, const int* in_sizes, int n_in,
                              void* d_out, int out_size)
{
    const float* x    = (const float*)d_in[0];
    const float* Wqkv = (const float*)d_in[1];
    const float* Wout = (const float*)d_in[2];
    const float* Wq   = (const float*)d_in[3];
    const float* bq   = (const float*)d_in[4];
    const float* Wk   = (const float*)d_in[5];
    const float* bk   = (const float*)d_in[6];
    const float* W1   = (const float*)d_in[7];
    const float* b1   = (const float*)d_in[8];
    const float* W2   = (const float*)d_in[9];
    const float* b2   = (const float*)d_in[10];
    const float* W3   = (const float*)d_in[11];
    const float* b3   = (const float*)d_in[12];
    float* out = (float*)d_out;

    // K1: qkv partials (split-K=2, 768 blocks), fused reduce+scatter
    gemm_k<3072, 2, false><<<dim3(48, 8, 2), 256>>>(x, Wqkv);
    rs_k<<<1536, 256>>>();
    // K2: a/c projections
    proj_k<<<dim3(8, 16, 2), 256>>>(Wq, bq, Wk, bk, W1, b1);
    // K3: MLP-scored causal flash attention -> g_ctx
    attn_k<<<dim3(16, 16), 256>>>(W2, b2, W3, b3);
    // K4: out partials (split-K=4, 512 blocks), reduce
    gemm_k<1024, 4, true><<<dim3(16, 8, 4), 256>>>(nullptr, Wout);
    ro_k<<<512, 256>>>(out);
}

// round 16
// speedup vs baseline: 1.4355x; 1.2086x over previous
#include <cuda_runtime.h>
#include <cuda_bf16.h>

#define N_TOK 512
#define DIMC  1024
#define HEADS 16
#define DH    64
#define PP    32
#define PH    16   // P2

typedef unsigned long long ull;

// ---------------- scratch (device globals; no allocations allowed) -----------
__device__ float g_q[HEADS * N_TOK * DH];
__device__ float g_k[HEADS * N_TOK * DH];
__device__ float g_v[HEADS * N_TOK * DH];
__device__ float g_a[HEADS * N_TOK * PP];
__device__ float g_c[HEADS * N_TOK * PP];    // b1 folded in
__device__ float g_ctx[N_TOK * DIMC];
__device__ float g_part[2 * N_TOK * 3072];   // split-K partials / attn partials
__device__ float g_ml[HEADS * 16 * 4 * 32 * 2];  // (m,l) per partial row

// heavy-first static schedule of the 40 (ib, chunk) work items per head
__device__ __constant__ int c_ib[40] = {
    3,4,5,6,7,7,8,8,9,9,10,10,11,11,11,12,12,12,13,13,13,14,14,14,15,15,15,15,
    2,6,10,14,  1,5,9,13,  0,4,8,12};
__device__ __constant__ int c_ch[40] = {
    0,0,0,0,0,1,0,1,0,1,0,1,0,1,2,0,1,2,0,1,2,0,1,2,0,1,2,3,
    0,1,2,3,  0,1,2,3,  0,1,2,3};

// ---------------- f32x2 packed-FMA helpers (Blackwell) -----------------------
__device__ __forceinline__ ull pack2(float a, float b) {
    ull r; asm("mov.b64 %0, {%1,%2};" : "=l"(r) : "f"(a), "f"(b)); return r;
}
__device__ __forceinline__ ull fma2(ull a, ull b, ull c) {
    ull d; asm("fma.rn.f32x2 %0, %1, %2, %3;" : "=l"(d) : "l"(a), "l"(b), "l"(c)); return d;
}
__device__ __forceinline__ ull mul2(ull a, ull b) {
    ull d; asm("mul.rn.f32x2 %0, %1, %2;" : "=l"(d) : "l"(a), "l"(b)); return d;
}
__device__ __forceinline__ float2 unpack2(ull v) {
    float2 r; asm("mov.b64 {%0,%1}, %2;" : "=f"(r.x), "=f"(r.y) : "l"(v)); return r;
}

// =============================================================================
// GEMM: 64x64 tile, 256 threads, 4x4 micro-tile, split-K over blockIdx.z.
// =============================================================================
template <int NCOLS, int SPLITK, bool ACTX>
__global__ __launch_bounds__(256) void gemm_k(const float* __restrict__ Ain,
                                              const float* __restrict__ B)
{
    const float* A = ACTX ? g_ctx : Ain;
    __shared__ __align__(16) float As[16][64];
    __shared__ __align__(16) float Bs[16][64];

    const int KPER = DIMC / SPLITK;
    int t  = threadIdx.x;
    int tx = t & 15, ty = t >> 4;
    int m0 = blockIdx.y * 64, n0 = blockIdx.x * 64;
    int z  = blockIdx.z;
    int lr = t >> 2, lc = (t & 3) << 2;

    ull acc[4][2];
#pragma unroll
    for (int i = 0; i < 4; i++) { acc[i][0] = 0ULL; acc[i][1] = 0ULL; }

    const float* Aptr = A + (size_t)(m0 + lr) * DIMC + z * KPER + lc;
    const float* Bptr = B + (size_t)(n0 + lr) * DIMC + z * KPER + lc;

    for (int k0 = 0; k0 < KPER; k0 += 16) {
        float4 av = *(const float4*)(Aptr + k0);
        float4 bv = *(const float4*)(Bptr + k0);
        As[lc + 0][lr] = av.x; As[lc + 1][lr] = av.y;
        As[lc + 2][lr] = av.z; As[lc + 3][lr] = av.w;
        Bs[lc + 0][lr] = bv.x; Bs[lc + 1][lr] = bv.y;
        Bs[lc + 2][lr] = bv.z; Bs[lc + 3][lr] = bv.w;
        __syncthreads();
#pragma unroll
        for (int kk = 0; kk < 16; kk++) {
            float4 a4 = *(const float4*)&As[kk][ty << 2];
            float4 b4 = *(const float4*)&Bs[kk][tx << 2];
            ull b01 = pack2(b4.x, b4.y), b23 = pack2(b4.z, b4.w);
            ull a0 = pack2(a4.x, a4.x), a1 = pack2(a4.y, a4.y);
            ull a2 = pack2(a4.z, a4.z), a3 = pack2(a4.w, a4.w);
            acc[0][0] = fma2(a0, b01, acc[0][0]); acc[0][1] = fma2(a0, b23, acc[0][1]);
            acc[1][0] = fma2(a1, b01, acc[1][0]); acc[1][1] = fma2(a1, b23, acc[1][1]);
            acc[2][0] = fma2(a2, b01, acc[2][0]); acc[2][1] = fma2(a2, b23, acc[2][1]);
            acc[3][0] = fma2(a3, b01, acc[3][0]); acc[3][1] = fma2(a3, b23, acc[3][1]);
        }
        __syncthreads();
    }

#pragma unroll
    for (int im = 0; im < 4; im++) {
        float2 c01 = unpack2(acc[im][0]);
        float2 c23 = unpack2(acc[im][1]);
        int m = m0 + (ty << 2) + im;
        size_t base = ((size_t)z * N_TOK + m) * NCOLS + n0 + (tx << 2);
        *(float4*)&g_part[base] = make_float4(c01.x, c01.y, c23.x, c23.y);
    }
}

// reduce 2 K1 partials + scatter qkv -> g_q/g_k/g_v.  o = d*48 + s*16 + h
__global__ __launch_bounds__(256) void rs_k()
{
    int i4 = blockIdx.x * 256 + threadIdx.x;
    int m  = i4 / 768;
    int o0 = (i4 - m * 768) * 4;
    float4 p0 = *(const float4*)&g_part[(size_t)m * 3072 + o0];
    float4 p1 = *(const float4*)&g_part[(size_t)(N_TOK + m) * 3072 + o0];
    float v[4] = {p0.x + p1.x, p0.y + p1.y, p0.z + p1.z, p0.w + p1.w};
#pragma unroll
    for (int io = 0; io < 4; io++) {
        int o  = o0 + io;
        int hh = o & 15;
        int s  = (o >> 4) % 3;
        int dd = o / 48;
        float* dst = (s == 0) ? g_q : (s == 1) ? g_k : g_v;
        dst[((hh * N_TOK) + m) * DH + dd] = v[io];
    }
}

// reduce 4 K4 partials -> final out
__global__ __launch_bounds__(256) void ro_k(float* __restrict__ out)
{
    int i4 = blockIdx.x * 256 + threadIdx.x;
    size_t off = (size_t)i4 * 4;
    float4 p0 = *(const float4*)&g_part[off];
    float4 p1 = *(const float4*)&g_part[off + (size_t)N_TOK * DIMC];
    float4 p2 = *(const float4*)&g_part[off + (size_t)2 * N_TOK * DIMC];
    float4 p3 = *(const float4*)&g_part[off + (size_t)3 * N_TOK * DIMC];
    *(float4*)&out[off] = make_float4(p0.x + p1.x + p2.x + p3.x,
                                      p0.y + p1.y + p2.y + p3.y,
                                      p0.z + p1.z + p2.z + p3.z,
                                      p0.w + p1.w + p2.w + p3.w);
}

// =============================================================================
// K2 : per-head projections (unchanged)
// =============================================================================
__global__ __launch_bounds__(256) void proj_k(const float* __restrict__ Wq_,
                                              const float* __restrict__ bq_,
                                              const float* __restrict__ Wk_,
                                              const float* __restrict__ bk_,
                                              const float* __restrict__ W1_,
                                              const float* __restrict__ b1_)
{
    __shared__ float Ws[PP][65];
    __shared__ float W1s[PP][33];
    __shared__ float qs[64][65];
    __shared__ float qps[64][33];
    __shared__ float bs[PP];
    __shared__ float b1s[PP];

    int t  = threadIdx.x;
    int z  = blockIdx.z, h = blockIdx.y, n0 = blockIdx.x * 64;
    const float* W    = z ? Wk_ : Wq_;
    const float* bias = z ? bk_ : bq_;
    const float* src  = z ? g_k : g_q;
    float*       dst  = z ? g_c : g_a;

    for (int idx = t; idx < PP * DH; idx += 256) { int p = idx >> 6, dd = idx & 63; Ws[p][dd] = W[idx]; }
    for (int idx = t; idx < PP * PP; idx += 256) { int q = idx >> 5, p = idx & 31; W1s[q][p] = W1_[q * (2 * PP) + z * PP + p]; }
    if (t < PP) { bs[t] = bias[t]; b1s[t] = b1_[t]; }
    for (int idx = t; idx < 64 * DH; idx += 256) {
        int nl = idx >> 6, dd = idx & 63;
        qs[nl][dd] = src[((h * N_TOK) + n0 + nl) * DH + dd];
    }
    __syncthreads();

    int p = t & 31, g8 = t >> 5;
#pragma unroll
    for (int m = 0; m < 8; m++) {
        int nl = g8 * 8 + m;
        float s = bs[p];
#pragma unroll 8
        for (int dd = 0; dd < DH; dd++) s += qs[nl][dd] * Ws[p][dd];
        qps[nl][p] = s;
    }
    __syncthreads();
#pragma unroll
    for (int m = 0; m < 8; m++) {
        int nl = g8 * 8 + m;
        float s = z ? b1s[p] : 0.f;
#pragma unroll 8
        for (int pp = 0; pp < PP; pp++) s += qps[nl][pp] * W1s[p][pp];
        dst[((h * N_TOK) + n0 + nl) * PP + p] = s;
    }
}

// =============================================================================
// K3a : attention PARTIAL. One block = (head, ib row-block, j-chunk of <=4 tiles).
// Emits unnormalized acc + (m, l) per row into g_part / g_ml.
// =============================================================================
__global__ __launch_bounds__(256, 2) void attn_part(const float* __restrict__ W2_,
                                                    const float* __restrict__ b2_,
                                                    const float* __restrict__ W3_,
                                                    const float* __restrict__ b3_)
{
    __shared__ __align__(16) float as_[PP][33];
    __shared__ __align__(16) float cs_[PP][33];
    __shared__ __align__(16) float Vs[32][65];
    __shared__ __align__(16) float Ss[32][36];
    __shared__ __align__(16) float W2c[PP][PH];
    __shared__ __align__(16) float w3s[PH];
    __shared__ __align__(16) float b2s[PH];
    __shared__ float m_s[32], l_s[32], sc_s[32], b3s;

    int t  = threadIdx.x;
    int h  = blockIdx.y;
    int wi = blockIdx.x;
    int ib = c_ib[wi], ch = c_ch[wi];
    int i0 = ib * 32;
    int jt0 = ch * 4;
    int jt1 = min(jt0 + 4, ib + 1);

    for (int idx = t; idx < PH * PP; idx += 256) { int q = idx >> 5, p = idx & 31; W2c[p][q] = W2_[idx]; }
    for (int idx = t; idx < 32 * PP; idx += 256) {
        int ii = idx >> 5, p = idx & 31;
        as_[p][ii] = g_a[((h * N_TOK) + i0 + ii) * PP + p];
    }
    if (t < 32) { m_s[t] = -1e30f; l_s[t] = 0.f; }
    if (t < PH) { w3s[t] = W3_[t]; b2s[t] = b2_[t]; }
    if (t == 0) { b3s = b3_[0]; }

    ull acc[8];
#pragma unroll
    for (int k = 0; k < 8; k++) acc[k] = 0ULL;

    int jc = t & 31, rbase = t >> 5;     // scoring: col jc, rows rbase+8r
    int dd = t & 63, prow = t >> 6;      // PV: col dd, rows prow+4k

    for (int jt = jt0; jt < jt1; jt++) {
        int j0 = jt * 32;
        __syncthreads();   // covers initial smem loads on first iteration
        for (int idx = t; idx < 32 * PP; idx += 256) {
            int jj = idx >> 5, p = idx & 31;
            cs_[p][jj] = g_c[((h * N_TOK) + j0 + jj) * PP + p];
        }
        for (int idx = t; idx < 32 * DH; idx += 256) {
            int jj = idx >> 6, d2 = idx & 63;
            Vs[jj][d2] = g_v[((h * N_TOK) + j0 + jj) * DH + d2];
        }
        __syncthreads();

        // ---- scoring
        ull h2p[4][8];
#pragma unroll
        for (int r = 0; r < 4; r++)
#pragma unroll
            for (int qq = 0; qq < 8; qq++) h2p[r][qq] = *(const ull*)&b2s[2 * qq];

#pragma unroll 4
        for (int p = 0; p < PP; p++) {
            float cj = cs_[p][jc];
            ull h11[4];
#pragma unroll
            for (int r = 0; r < 4; r++) {
                float h1 = fmaxf(as_[p][rbase + 8 * r] + cj, 0.f);
                h11[r] = pack2(h1, h1);
            }
            const ull* wrow = (const ull*)&W2c[p][0];
#pragma unroll
            for (int qq = 0; qq < 8; qq++) {
                ull w2 = wrow[qq];
                h2p[0][qq] = fma2(h11[0], w2, h2p[0][qq]);
                h2p[1][qq] = fma2(h11[1], w2, h2p[1][qq]);
                h2p[2][qq] = fma2(h11[2], w2, h2p[2][qq]);
                h2p[3][qq] = fma2(h11[3], w2, h2p[3][qq]);
            }
        }
#pragma unroll
        for (int r = 0; r < 4; r++) {
            float s = b3s;
#pragma unroll
            for (int qq = 0; qq < 8; qq++) {
                float2 hq = unpack2(h2p[r][qq]);
                s += w3s[2 * qq]     * fmaxf(hq.x, 0.f);
                s += w3s[2 * qq + 1] * fmaxf(hq.y, 0.f);
            }
            int irow = rbase + 8 * r;
            if (j0 + jc > i0 + irow) s = -1e30f;
            Ss[irow][jc] = s;
        }
        __syncthreads();

        // ---- online softmax
        {
            int row = t >> 3, c8 = t & 7;
            float mx = -1e30f;
#pragma unroll
            for (int u = 0; u < 4; u++) mx = fmaxf(mx, Ss[row][c8 * 4 + u]);
            mx = fmaxf(mx, __shfl_xor_sync(0xffffffffu, mx, 1));
            mx = fmaxf(mx, __shfl_xor_sync(0xffffffffu, mx, 2));
            mx = fmaxf(mx, __shfl_xor_sync(0xffffffffu, mx, 4));
            float mnew = fmaxf(m_s[row], mx);
            float sum = 0.f;
#pragma unroll
            for (int u = 0; u < 4; u++) {
                float e = __expf(Ss[row][c8 * 4 + u] - mnew);
                Ss[row][c8 * 4 + u] = e;
                sum += e;
            }
            sum += __shfl_xor_sync(0xffffffffu, sum, 1);
            sum += __shfl_xor_sync(0xffffffffu, sum, 2);
            sum += __shfl_xor_sync(0xffffffffu, sum, 4);
            if (c8 == 0) {
                float scl = __expf(m_s[row] - mnew);
                sc_s[row] = scl;
                l_s[row]  = l_s[row] * scl + sum;
                m_s[row]  = mnew;
            }
        }
        __syncthreads();

        // ---- rescale + P@V
#pragma unroll
        for (int k = 0; k < 8; k++) {
            float scl = sc_s[prow + 4 * k];
            acc[k] = mul2(acc[k], pack2(scl, scl));
        }
#pragma unroll 8
        for (int j = 0; j < 32; j += 2) {
            ull v2 = pack2(Vs[j][dd], Vs[j + 1][dd]);
#pragma unroll
            for (int k = 0; k < 8; k++) {
                int ir = prow + 4 * k;
                ull pj = *(const ull*)&Ss[ir][j];
                acc[k] = fma2(pj, v2, acc[k]);
            }
        }
    }

    __syncthreads();
    // ---- emit partial (unnormalized)
    int pbase = ((h * 16 + ib) * 4 + ch) * 32;
#pragma unroll
    for (int k = 0; k < 8; k++) {
        int ir = prow + 4 * k;
        float2 a2 = unpack2(acc[k]);
        g_part[(size_t)(pbase + ir) * 64 + dd] = a2.x + a2.y;
    }
    if (t < 32) {
        g_ml[(pbase + t) * 2 + 0] = m_s[t];
        g_ml[(pbase + t) * 2 + 1] = l_s[t];
    }
}

// =============================================================================
// K3b : combine <=4 partials per (h, ib) -> g_ctx
// =============================================================================
__global__ __launch_bounds__(256) void attn_comb()
{
    __shared__ float wgt[4][32];
    __shared__ float linv[32];

    int h  = blockIdx.y, ib = blockIdx.x;
    int nc = (ib + 4) >> 2;          // ceil((ib+1)/4)
    int i0 = ib * 32;
    int t  = threadIdx.x, dd = t & 63, pr = t >> 6;
    int pb = (h * 16 + ib) * 4;

    if (t < 32) {
        float M = -1e30f;
        float mv[4];
#pragma unroll
        for (int c = 0; c < 4; c++) {
            mv[c] = (c < nc) ? g_ml[(pb + c) * 32 * 2 + t * 2] : -1e30f;
            M = fmaxf(M, mv[c]);
        }
        float L = 0.f;
#pragma unroll
        for (int c = 0; c < 4; c++) {
            float w = (c < nc) ? __expf(mv[c] - M) : 0.f;
            wgt[c][t] = w;
            if (c < nc) L += g_ml[(pb + c) * 32 * 2 + t * 2 + 1] * w;
        }
        linv[t] = __frcp_rn(L);
    }
    __syncthreads();

#pragma unroll
    for (int k = 0; k < 8; k++) {
        int row = pr + 4 * k;
        float s = 0.f;
#pragma unroll
        for (int c = 0; c < 4; c++) {
            if (c < nc)
                s += g_part[(size_t)((pb + c) * 32 + row) * 64 + dd] * wgt[c][row];
        }
        g_ctx[(size_t)(i0 + row) * DIMC + h * DH + dd] = s * linv[row];
    }
}

// =============================================================================
extern "C" void kernel_launch(void* const* d_in, const int* in_sizes, int n_in,
                              void* d_out, int out_size)
{
    const float* x    = (const float*)d_in[0];
    const float* Wqkv = (const float*)d_in[1];
    const float* Wout = (const float*)d_in[2];
    const float* Wq   = (const float*)d_in[3];
    const float* bq   = (const float*)d_in[4];
    const float* Wk   = (const float*)d_in[5];
    const float* bk   = (const float*)d_in[6];
    const float* W1   = (const float*)d_in[7];
    const float* b1   = (const float*)d_in[8];
    const float* W2   = (const float*)d_in[9];
    const float* b2   = (const float*)d_in[10];
    const float* W3   = (const float*)d_in[11];
    const float* b3   = (const float*)d_in[12];
    float* out = (float*)d_out;

    // K1: qkv partials (split-K=2), fused reduce+scatter
    gemm_k<3072, 2, false><<<dim3(48, 8, 2), 256>>>(x, Wqkv);
    rs_k<<<1536, 256>>>();
    // K2: a/c projections
    proj_k<<<dim3(8, 16, 2), 256>>>(Wq, bq, Wk, bk, W1, b1);
    // K3: split-j MLP-scored causal flash attention (640 uniform blocks) + combine
    attn_part<<<dim3(40, 16), 256>>>(W2, b2, W3, b3);
    attn_comb<<<dim3(16, 16), 256>>>();
    // K4: out partials (split-K=4), reduce
    gemm_k<1024, 4, true><<<dim3(16, 8, 4), 256>>>(nullptr, Wout);
    ro_k<<<512, 256>>>(out);
}